// round 7
// baseline (speedup 1.0000x reference)
#include <cuda_runtime.h>
#include <math.h>
#include <stdint.h>

#define T_SEQ 4096
#define C_DIM 2048
#define KV_DIM 512
#define QKV_N 3072
#define NH 16
#define NKV 4
#define HD 128
#define HALF 64
#define WIN 64
#define KDIM 2048
#define KT 64                 // 2048 / 32

// Scratch (no runtime allocation allowed)
__device__ float g_Q[T_SEQ * C_DIM];
__device__ float g_K[T_SEQ * KV_DIM];
__device__ float g_V[T_SEQ * KV_DIM];
__device__ float g_AO[T_SEQ * C_DIM];
__device__ float g_XR[T_SEQ * C_DIM];          // tf32-rounded x
__device__ float g_W[QKV_N * KDIM];            // tf32-rounded [wq|wk|wv]^T  [N][K]
__device__ float g_WO[C_DIM * KDIM];           // tf32-rounded wo^T          [N][K]
__device__ float2 g_RC[T_SEQ * HALF];          // rope (cos,sin) table

__device__ __forceinline__ uint32_t f2tf32(float f) {
    uint32_t u;
    asm("cvt.rna.tf32.f32 %0, %1;" : "=r"(u) : "f"(f));
    return u;
}
__device__ __forceinline__ float rna(float f) { return __uint_as_float(f2tf32(f)); }

// ---------------------------------------------------------------------------
// One-time prep kernels
// ---------------------------------------------------------------------------
__global__ void rc_kernel() {
    int idx = blockIdx.x * blockDim.x + threadIdx.x;
    if (idx >= T_SEQ * HALF) return;
    int t = idx >> 6;
    int j = idx & 63;
    float inv = powf(10000.0f, -(float)j / (float)HALF);
    float s, c;
    sincosf((float)t * inv, &s, &c);
    g_RC[idx] = make_float2(c, s);
}

__global__ void round_copy4(const float4* __restrict__ src, float4* __restrict__ dst,
                            int n4) {
    int i = blockIdx.x * blockDim.x + threadIdx.x;
    if (i >= n4) return;
    float4 v = src[i];
    dst[i] = make_float4(rna(v.x), rna(v.y), rna(v.z), rna(v.w));
}

// Transpose + round: g_W[n][k] = rna(src[k][n]); src picked per n-region.
__global__ void build_wt(const float* __restrict__ wq, const float* __restrict__ wk,
                         const float* __restrict__ wv) {
    __shared__ float tile[32][33];
    int k0 = blockIdx.x * 32;
    int n0 = blockIdx.y * 32;
    int tx = threadIdx.x, ty = threadIdx.y;
    const float* src;
    int nb, noff;
    if (n0 < C_DIM)               { src = wq; nb = C_DIM;  noff = 0; }
    else if (n0 < C_DIM + KV_DIM) { src = wk; nb = KV_DIM; noff = C_DIM; }
    else                          { src = wv; nb = KV_DIM; noff = C_DIM + KV_DIM; }
#pragma unroll
    for (int j = 0; j < 4; j++)
        tile[ty + j * 8][tx] =
            rna(src[(size_t)(k0 + ty + j * 8) * nb + (n0 - noff + tx)]);
    __syncthreads();
#pragma unroll
    for (int j = 0; j < 4; j++)
        g_W[(size_t)(n0 + ty + j * 8) * KDIM + k0 + tx] = tile[tx][ty + j * 8];
}

__global__ void build_wot(const float* __restrict__ wo) {
    __shared__ float tile[32][33];
    int k0 = blockIdx.x * 32;
    int n0 = blockIdx.y * 32;
    int tx = threadIdx.x, ty = threadIdx.y;
#pragma unroll
    for (int j = 0; j < 4; j++)
        tile[ty + j * 8][tx] = rna(wo[(size_t)(k0 + ty + j * 8) * C_DIM + n0 + tx]);
    __syncthreads();
#pragma unroll
    for (int j = 0; j < 4; j++)
        g_WO[(size_t)(n0 + ty + j * 8) * KDIM + k0 + tx] = tile[tx][ty + j * 8];
}

// ---------------------------------------------------------------------------
// TF32 mma.sync GEMM: C[M,N] = A[M,K] @ Bt[N,K]^T, inputs tf32-pre-rounded.
// CTA tile 128x128x32, 128 threads (4 warps 2x2), warp tile 64x64.
// Both tiles K-major [row][32] with stride 36 -> conflict-free frag loads.
// cp.async 3-stage pipeline, 2 CTAs/SM.
// mode 0: plain store. mode 1: QKV epilogue (rope + route to g_Q/g_K/g_V).
// ---------------------------------------------------------------------------
#define STAGES 3
#define SROW 36
#define STG_FLOATS (2 * 128 * SROW)              // A + B tiles: 9216 floats
#define SMEM_BYTES (STAGES * STG_FLOATS * 4)     // 110592

__device__ __forceinline__ void cp16(uint32_t dst, const float* src) {
    asm volatile("cp.async.ca.shared.global [%0], [%1], 16;\n" :: "r"(dst), "l"(src));
}

__device__ __forceinline__ void mma_tf32(float c[4], const uint32_t a[4],
                                         const uint32_t b[2]) {
    asm volatile(
        "mma.sync.aligned.m16n8k8.row.col.f32.tf32.tf32.f32 "
        "{%0,%1,%2,%3}, {%4,%5,%6,%7}, {%8,%9}, {%0,%1,%2,%3};\n"
        : "+f"(c[0]), "+f"(c[1]), "+f"(c[2]), "+f"(c[3])
        : "r"(a[0]), "r"(a[1]), "r"(a[2]), "r"(a[3]), "r"(b[0]), "r"(b[1]));
}

__device__ __forceinline__ void issue_stage(const float* __restrict__ ag,
                                            const float* __restrict__ bg, int kt,
                                            uint32_t smem_u) {
    uint32_t base = smem_u + (uint32_t)(kt % STAGES) * (STG_FLOATS * 4);
    const int tid = threadIdx.x;
    uint32_t arow = base + (uint32_t)tid * (SROW * 4);
    uint32_t brow = arow + 128 * SROW * 4;
    const float* a = ag + (size_t)kt * 32;
    const float* b = bg + (size_t)kt * 32;
#pragma unroll
    for (int v = 0; v < 8; v++) {
        cp16(arow + v * 16, a + v * 4);
        cp16(brow + v * 16, b + v * 4);
    }
    asm volatile("cp.async.commit_group;\n" ::);
}

__device__ __forceinline__ void qkv_store(int t, int col, float v0, float v1) {
    if (col < C_DIM) {
        int jj = (col & 127) >> 1;
        float2 cs = g_RC[t * HALF + jj];
        *(float2*)&g_Q[(size_t)t * C_DIM + col] =
            make_float2(v0 * cs.x - v1 * cs.y, v0 * cs.y + v1 * cs.x);
    } else if (col < C_DIM + KV_DIM) {
        int kc = col - C_DIM;
        int jj = (kc & 127) >> 1;
        float2 cs = g_RC[t * HALF + jj];
        *(float2*)&g_K[(size_t)t * KV_DIM + kc] =
            make_float2(v0 * cs.x - v1 * cs.y, v0 * cs.y + v1 * cs.x);
    } else {
        int vc = col - C_DIM - KV_DIM;
        *(float2*)&g_V[(size_t)t * KV_DIM + vc] = make_float2(v0, v1);
    }
}

__global__ void __launch_bounds__(128, 2) gemm_tf32(const float* __restrict__ A,
                                                    const float* __restrict__ Bt,
                                                    float* __restrict__ C,
                                                    int N, int mode) {
    extern __shared__ float smem[];
    uint32_t smem_u;
    asm("{.reg .u64 t; cvta.to.shared.u64 t, %1; cvt.u32.u64 %0, t;}"
        : "=r"(smem_u) : "l"(smem));

    const int tid = threadIdx.x;
    const int bm = blockIdx.y * 128;
    const int bn = blockIdx.x * 128;
    const int warp = tid >> 5;
    const int lane = tid & 31;
    const int wm = warp >> 1;       // 0..1
    const int wn = warp & 1;        // 0..1
    const int g  = lane >> 2;       // 0..7
    const int tg = lane & 3;        // 0..3

    const float* ag = A + (size_t)(bm + tid) * KDIM;
    const float* bg = Bt + (size_t)(bn + tid) * KDIM;

    float acc[4][8][4];
#pragma unroll
    for (int i = 0; i < 4; i++)
#pragma unroll
        for (int j = 0; j < 8; j++)
#pragma unroll
            for (int r = 0; r < 4; r++) acc[i][j][r] = 0.f;

    issue_stage(ag, bg, 0, smem_u);
    issue_stage(ag, bg, 1, smem_u);

    for (int kt = 0; kt < KT; kt++) {
        if (kt < KT - 1)
            asm volatile("cp.async.wait_group 1;\n" ::);
        else
            asm volatile("cp.async.wait_group 0;\n" ::);
        __syncthreads();
        // stage (kt+2)%3 == (kt-1)%3: consumed by all warps before this barrier
        if (kt + 2 < KT) issue_stage(ag, bg, kt + 2, smem_u);

        const uint32_t* su =
            (const uint32_t*)(smem + (size_t)(kt % STAGES) * STG_FLOATS);
        const uint32_t* bu = su + 128 * SROW;

#pragma unroll
        for (int ks = 0; ks < 4; ks++) {
            const int kk = ks * 8 + tg;
            uint32_t af[4][4], bf[8][2];
#pragma unroll
            for (int i = 0; i < 4; i++) {
                int r0 = (wm * 64 + i * 16 + g) * SROW;
                af[i][0] = su[r0 + kk];
                af[i][1] = su[r0 + 8 * SROW + kk];
                af[i][2] = su[r0 + kk + 4];
                af[i][3] = su[r0 + 8 * SROW + kk + 4];
            }
#pragma unroll
            for (int j = 0; j < 8; j++) {
                int c0 = (wn * 64 + j * 8 + g) * SROW;
                bf[j][0] = bu[c0 + kk];
                bf[j][1] = bu[c0 + kk + 4];
            }
#pragma unroll
            for (int i = 0; i < 4; i++)
#pragma unroll
                for (int j = 0; j < 8; j++) mma_tf32(acc[i][j], af[i], bf[j]);
        }
    }

    if (mode == 0) {
#pragma unroll
        for (int i = 0; i < 4; i++)
#pragma unroll
            for (int j = 0; j < 8; j++) {
                int row = bm + wm * 64 + i * 16 + g;
                int col = bn + wn * 64 + j * 8 + 2 * tg;
                *(float2*)(C + (size_t)row * N + col) =
                    make_float2(acc[i][j][0], acc[i][j][1]);
                *(float2*)(C + (size_t)(row + 8) * N + col) =
                    make_float2(acc[i][j][2], acc[i][j][3]);
            }
    } else {
#pragma unroll
        for (int i = 0; i < 4; i++)
#pragma unroll
            for (int j = 0; j < 8; j++) {
                int row = bm + wm * 64 + i * 16 + g;
                int col = bn + wn * 64 + j * 8 + 2 * tg;
                qkv_store(row, col, acc[i][j][0], acc[i][j][1]);
                qkv_store(row + 8, col, acc[i][j][2], acc[i][j][3]);
            }
    }
}

// ---------------------------------------------------------------------------
// Sliding-window attention: one warp handles 4 adjacent queries of one head,
// sharing each K/V float4 load. Branchy online softmax. sink cancels; ignored.
// Output is tf32-rounded (feeds final GEMM directly).
// ---------------------------------------------------------------------------
__global__ void __launch_bounds__(256) attn_kernel(const float* __restrict__ Q,
                                                   const float* __restrict__ K,
                                                   const float* __restrict__ V,
                                                   float* __restrict__ O) {
    const int warp = threadIdx.x >> 5;
    const int lane = threadIdx.x & 31;
    const int tq = (blockIdx.x * 8 + warp) * 4;
    const int h = blockIdx.y;
    const int kh = h >> 2;
    const float scale = 0.08838834764831845f;

    float4 q[4];
#pragma unroll
    for (int i = 0; i < 4; i++)
        q[i] = *(const float4*)(Q + (size_t)(tq + i) * C_DIM + h * HD + lane * 4);

    float m[4] = {-1e30f, -1e30f, -1e30f, -1e30f};
    float l[4] = {0.f, 0.f, 0.f, 0.f};
    float4 a[4];
#pragma unroll
    for (int i = 0; i < 4; i++) a[i] = make_float4(0.f, 0.f, 0.f, 0.f);

    int s0 = tq - WIN;      if (s0 < 0) s0 = 0;
    int s1 = tq + 3 + WIN;  if (s1 > T_SEQ - 1) s1 = T_SEQ - 1;

    for (int s = s0; s <= s1; s++) {
        float4 kv = *(const float4*)(K + (size_t)s * KV_DIM + kh * HD + lane * 4);
        float4 vv = *(const float4*)(V + (size_t)s * KV_DIM + kh * HD + lane * 4);
#pragma unroll
        for (int i = 0; i < 4; i++) {
            int t = tq + i;
            if (s < t - WIN || s > t + WIN) continue;  // warp-uniform
            float d = q[i].x * kv.x + q[i].y * kv.y + q[i].z * kv.z + q[i].w * kv.w;
#pragma unroll
            for (int o = 16; o > 0; o >>= 1) d += __shfl_xor_sync(0xffffffffu, d, o);
            d *= scale;
            if (d <= m[i]) {
                float p = __expf(d - m[i]);
                l[i] += p;
                a[i].x += p * vv.x;
                a[i].y += p * vv.y;
                a[i].z += p * vv.z;
                a[i].w += p * vv.w;
            } else {
                float corr = __expf(m[i] - d);
                m[i] = d;
                l[i] = l[i] * corr + 1.f;
                a[i].x = a[i].x * corr + vv.x;
                a[i].y = a[i].y * corr + vv.y;
                a[i].z = a[i].z * corr + vv.z;
                a[i].w = a[i].w * corr + vv.w;
            }
        }
    }
#pragma unroll
    for (int i = 0; i < 4; i++) {
        float inv = 1.f / l[i];
        *(float4*)(O + (size_t)(tq + i) * C_DIM + h * HD + lane * 4) =
            make_float4(rna(a[i].x * inv), rna(a[i].y * inv),
                        rna(a[i].z * inv), rna(a[i].w * inv));
    }
}

// ---------------------------------------------------------------------------
extern "C" void kernel_launch(void* const* d_in, const int* in_sizes, int n_in,
                              void* d_out, int out_size) {
    const float* x  = (const float*)d_in[0];
    const float* wq = (const float*)d_in[1];
    const float* wk = (const float*)d_in[2];
    const float* wv = (const float*)d_in[3];
    const float* wo = (const float*)d_in[4];
    // d_in[5] = sink: constant per softmax row -> cancels; ignored.
    float* out = (float*)d_out;

    float *Q, *Kp, *Vp, *AO, *XR, *W, *WO;
    cudaGetSymbolAddress((void**)&Q,  g_Q);
    cudaGetSymbolAddress((void**)&Kp, g_K);
    cudaGetSymbolAddress((void**)&Vp, g_V);
    cudaGetSymbolAddress((void**)&AO, g_AO);
    cudaGetSymbolAddress((void**)&XR, g_XR);
    cudaGetSymbolAddress((void**)&W,  g_W);
    cudaGetSymbolAddress((void**)&WO, g_WO);

    // one-time prep: rope table + tf32 rounding + weight transposes
    rc_kernel<<<(T_SEQ * HALF + 255) / 256, 256>>>();
    {
        int n4 = T_SEQ * C_DIM / 4;
        round_copy4<<<(n4 + 255) / 256, 256>>>((const float4*)x, (float4*)XR, n4);
        build_wt<<<dim3(KDIM / 32, QKV_N / 32), dim3(32, 8)>>>(wq, wk, wv);
        build_wot<<<dim3(KDIM / 32, C_DIM / 32), dim3(32, 8)>>>(wo);
    }

    cudaFuncSetAttribute(gemm_tf32, cudaFuncAttributeMaxDynamicSharedMemorySize,
                         SMEM_BYTES);

    // QKV projection (fused, rope in epilogue)
    gemm_tf32<<<dim3(QKV_N / 128, T_SEQ / 128), 128, SMEM_BYTES>>>(XR, W, nullptr,
                                                                   QKV_N, 1);

    attn_kernel<<<dim3(T_SEQ / 32, NH), 256>>>(Q, Kp, Vp, AO);

    // output projection
    gemm_tf32<<<dim3(C_DIM / 128, T_SEQ / 128), 128, SMEM_BYTES>>>(AO, WO, out,
                                                                   C_DIM, 0);
}

// round 8
// speedup vs baseline: 1.8259x; 1.8259x over previous
#include <cuda_runtime.h>
#include <math.h>
#include <stdint.h>

#define T_SEQ 4096
#define C_DIM 2048
#define KV_DIM 512
#define QKV_N 3072
#define NH 16
#define NKV 4
#define HD 128
#define HALF 64
#define WIN 64
#define KDIM 2048
#define KT 64                 // 2048 / 32

// Scratch (no runtime allocation allowed)
__device__ float g_Q[T_SEQ * C_DIM];
__device__ float g_K[T_SEQ * KV_DIM];
__device__ float g_V[T_SEQ * KV_DIM];
__device__ float g_AO[T_SEQ * C_DIM];
__device__ float g_XR[T_SEQ * C_DIM];          // tf32-rounded x
__device__ float g_W[C_DIM * QKV_N];           // tf32-rounded [wq|wk|wv]  [K][N]
__device__ float g_WO[C_DIM * C_DIM];          // tf32-rounded wo          [K][N]
__device__ float2 g_RC[T_SEQ * HALF];          // rope (cos,sin) table

__device__ __forceinline__ uint32_t f2tf32(float f) {
    uint32_t u;
    asm("cvt.rna.tf32.f32 %0, %1;" : "=r"(u) : "f"(f));
    return u;
}
__device__ __forceinline__ float rna(float f) { return __uint_as_float(f2tf32(f)); }

// ---------------------------------------------------------------------------
// One-time prep kernels
// ---------------------------------------------------------------------------
__global__ void rc_kernel() {
    int idx = blockIdx.x * blockDim.x + threadIdx.x;
    if (idx >= T_SEQ * HALF) return;
    int t = idx >> 6;
    int j = idx & 63;
    float inv = powf(10000.0f, -(float)j / (float)HALF);
    float s, c;
    sincosf((float)t * inv, &s, &c);
    g_RC[idx] = make_float2(c, s);
}

__global__ void round_copy4(const float4* __restrict__ src, float4* __restrict__ dst,
                            int n4) {
    int i = blockIdx.x * blockDim.x + threadIdx.x;
    if (i >= n4) return;
    float4 v = src[i];
    dst[i] = make_float4(rna(v.x), rna(v.y), rna(v.z), rna(v.w));
}

__global__ void build_w(const float4* __restrict__ wq, const float4* __restrict__ wk,
                        const float4* __restrict__ wv, float4* __restrict__ W) {
    int i = blockIdx.x * blockDim.x + threadIdx.x;   // over C_DIM*QKV_N/4
    if (i >= C_DIM * QKV_N / 4) return;
    int c4 = i % (QKV_N / 4);
    int k  = i / (QKV_N / 4);
    int col = c4 * 4;
    float4 v;
    if (col < C_DIM)               v = wq[(k * C_DIM + col) >> 2];
    else if (col < C_DIM + KV_DIM) v = wk[(k * KV_DIM + col - C_DIM) >> 2];
    else                           v = wv[(k * KV_DIM + col - C_DIM - KV_DIM) >> 2];
    W[i] = make_float4(rna(v.x), rna(v.y), rna(v.z), rna(v.w));
}

// ---------------------------------------------------------------------------
// TF32 mma.sync GEMM: C[M,N] = A[M,K] @ B[K,N], inputs tf32-pre-rounded.
// CTA tile 128x128x32, 256 threads (8 warps 2x4), warp tile 64x32.
// cp.async 3-stage pipeline, 2 CTAs/SM (explicit max smem carveout).
// mode 0: plain store. mode 1: QKV epilogue (rope + route to g_Q/g_K/g_V).
// ---------------------------------------------------------------------------
#define STAGES 3
#define SA 36
#define SB 132
#define STG_FLOATS (128 * SA + 32 * SB)   // 8832 floats = 35328 B
#define SMEM_BYTES (STAGES * STG_FLOATS * 4)

__device__ __forceinline__ void cp16(uint32_t dst, const float* src) {
    asm volatile("cp.async.cg.shared.global [%0], [%1], 16;\n" :: "r"(dst), "l"(src));
}

__device__ __forceinline__ void mma_tf32(float c[4], const uint32_t a[4],
                                         const uint32_t b[2]) {
    asm volatile(
        "mma.sync.aligned.m16n8k8.row.col.f32.tf32.tf32.f32 "
        "{%0,%1,%2,%3}, {%4,%5,%6,%7}, {%8,%9}, {%0,%1,%2,%3};\n"
        : "+f"(c[0]), "+f"(c[1]), "+f"(c[2]), "+f"(c[3])
        : "r"(a[0]), "r"(a[1]), "r"(a[2]), "r"(a[3]), "r"(b[0]), "r"(b[1]));
}

__device__ __forceinline__ void qkv_store(int t, int col, float v0, float v1) {
    if (col < C_DIM) {
        int jj = (col & 127) >> 1;
        float2 cs = g_RC[t * HALF + jj];
        *(float2*)&g_Q[(size_t)t * C_DIM + col] =
            make_float2(v0 * cs.x - v1 * cs.y, v0 * cs.y + v1 * cs.x);
    } else if (col < C_DIM + KV_DIM) {
        int kc = col - C_DIM;
        int jj = (kc & 127) >> 1;
        float2 cs = g_RC[t * HALF + jj];
        *(float2*)&g_K[(size_t)t * KV_DIM + kc] =
            make_float2(v0 * cs.x - v1 * cs.y, v0 * cs.y + v1 * cs.x);
    } else {
        int vc = col - C_DIM - KV_DIM;
        *(float2*)&g_V[(size_t)t * KV_DIM + vc] = make_float2(v0, v1);
    }
}

__global__ void __launch_bounds__(256, 2) gemm_tf32(const float* __restrict__ A,
                                                    const float* __restrict__ B,
                                                    float* __restrict__ C,
                                                    int N, int mode) {
    extern __shared__ float smem[];
    uint32_t smem_u;
    asm("{.reg .u64 t; cvta.to.shared.u64 t, %1; cvt.u32.u64 %0, t;}"
        : "=r"(smem_u) : "l"(smem));

    const int tid = threadIdx.x;
    const int bm = blockIdx.y * 128;
    const int bn = blockIdx.x * 128;
    const int warp = tid >> 5;
    const int lane = tid & 31;
    const int wm = warp >> 2;
    const int wn = warp & 3;
    const int g  = lane >> 2;
    const int tg = lane & 3;

    // advancing global pointers (one add per stage; minimal live regs)
    const int arow = tid >> 3;
    const int acol = (tid & 7) << 2;
    const int brow = tid >> 5;
    const int bcol = (tid & 31) << 2;
    const float* aptr = A + (size_t)(bm + arow) * KDIM + acol;
    const float* bptr = B + (size_t)brow * N + bn + bcol;
    const size_t bstep = (size_t)32 * N;

    // smem stage write bases (fixed offsets per thread)
    const uint32_t aoff = (uint32_t)((arow * SA + acol) * 4);
    const uint32_t boff = (uint32_t)((128 * SA + brow * SB + bcol) * 4);

    float acc[4][4][4];
#pragma unroll
    for (int i = 0; i < 4; i++)
#pragma unroll
        for (int j = 0; j < 4; j++)
#pragma unroll
            for (int r = 0; r < 4; r++) acc[i][j][r] = 0.f;

    // prologue: stages 0,1
#pragma unroll
    for (int s = 0; s < STAGES - 1; s++) {
        uint32_t base = smem_u + (uint32_t)s * (STG_FLOATS * 4);
#pragma unroll
        for (int p = 0; p < 4; p++)
            cp16(base + aoff + p * (32 * SA * 4), aptr + (size_t)p * 32 * KDIM);
#pragma unroll
        for (int p = 0; p < 4; p++)
            cp16(base + boff + p * (8 * SB * 4), bptr + (size_t)p * 8 * N);
        asm volatile("cp.async.commit_group;\n" ::);
        aptr += 32;
        bptr += bstep;
    }

    int st = 0;          // consume stage index
    int wst = STAGES - 1; // write stage index
    for (int kt = 0; kt < KT; kt++) {
        if (kt < KT - 1)
            asm volatile("cp.async.wait_group 1;\n" ::);
        else
            asm volatile("cp.async.wait_group 0;\n" ::);
        __syncthreads();

        if (kt + STAGES - 1 < KT) {
            uint32_t base = smem_u + (uint32_t)wst * (STG_FLOATS * 4);
#pragma unroll
            for (int p = 0; p < 4; p++)
                cp16(base + aoff + p * (32 * SA * 4), aptr + (size_t)p * 32 * KDIM);
#pragma unroll
            for (int p = 0; p < 4; p++)
                cp16(base + boff + p * (8 * SB * 4), bptr + (size_t)p * 8 * N);
            asm volatile("cp.async.commit_group;\n" ::);
            aptr += 32;
            bptr += bstep;
            wst = (wst == STAGES - 1) ? 0 : wst + 1;
        }

        const uint32_t* su = (const uint32_t*)(smem + (size_t)st * STG_FLOATS);
        const uint32_t* bu = su + 128 * SA;
        st = (st == STAGES - 1) ? 0 : st + 1;

#pragma unroll
        for (int ks = 0; ks < 4; ks++) {
            const int kk = ks * 8 + tg;
            uint32_t af[4][4], bf[4][2];
#pragma unroll
            for (int i = 0; i < 4; i++) {
                int r0 = (wm * 64 + i * 16 + g) * SA;
                af[i][0] = su[r0 + kk];
                af[i][1] = su[r0 + 8 * SA + kk];
                af[i][2] = su[r0 + kk + 4];
                af[i][3] = su[r0 + 8 * SA + kk + 4];
            }
#pragma unroll
            for (int j = 0; j < 4; j++) {
                int c0 = wn * 32 + j * 8 + g;
                bf[j][0] = bu[kk * SB + c0];
                bf[j][1] = bu[(kk + 4) * SB + c0];
            }
#pragma unroll
            for (int i = 0; i < 4; i++)
#pragma unroll
                for (int j = 0; j < 4; j++) mma_tf32(acc[i][j], af[i], bf[j]);
        }
    }

    if (mode == 0) {
#pragma unroll
        for (int i = 0; i < 4; i++)
#pragma unroll
            for (int j = 0; j < 4; j++) {
                int row = bm + wm * 64 + i * 16 + g;
                int col = bn + wn * 32 + j * 8 + 2 * tg;
                *(float2*)(C + (size_t)row * N + col) =
                    make_float2(acc[i][j][0], acc[i][j][1]);
                *(float2*)(C + (size_t)(row + 8) * N + col) =
                    make_float2(acc[i][j][2], acc[i][j][3]);
            }
    } else {
#pragma unroll
        for (int i = 0; i < 4; i++)
#pragma unroll
            for (int j = 0; j < 4; j++) {
                int row = bm + wm * 64 + i * 16 + g;
                int col = bn + wn * 32 + j * 8 + 2 * tg;
                qkv_store(row, col, acc[i][j][0], acc[i][j][1]);
                qkv_store(row + 8, col, acc[i][j][2], acc[i][j][3]);
            }
    }
}

// ---------------------------------------------------------------------------
// Sliding-window attention: one warp handles 4 adjacent queries of one head,
// sharing each K/V float4 load. Branchy online softmax. sink cancels; ignored.
// Output is tf32-rounded (feeds final GEMM directly).
// ---------------------------------------------------------------------------
__global__ void __launch_bounds__(256) attn_kernel(const float* __restrict__ Q,
                                                   const float* __restrict__ K,
                                                   const float* __restrict__ V,
                                                   float* __restrict__ O) {
    const int warp = threadIdx.x >> 5;
    const int lane = threadIdx.x & 31;
    const int tq = (blockIdx.x * 8 + warp) * 4;
    const int h = blockIdx.y;
    const int kh = h >> 2;
    const float scale = 0.08838834764831845f;

    float4 q[4];
#pragma unroll
    for (int i = 0; i < 4; i++)
        q[i] = *(const float4*)(Q + (size_t)(tq + i) * C_DIM + h * HD + lane * 4);

    float m[4] = {-1e30f, -1e30f, -1e30f, -1e30f};
    float l[4] = {0.f, 0.f, 0.f, 0.f};
    float4 a[4];
#pragma unroll
    for (int i = 0; i < 4; i++) a[i] = make_float4(0.f, 0.f, 0.f, 0.f);

    int s0 = tq - WIN;      if (s0 < 0) s0 = 0;
    int s1 = tq + 3 + WIN;  if (s1 > T_SEQ - 1) s1 = T_SEQ - 1;

    for (int s = s0; s <= s1; s++) {
        float4 kv = *(const float4*)(K + (size_t)s * KV_DIM + kh * HD + lane * 4);
        float4 vv = *(const float4*)(V + (size_t)s * KV_DIM + kh * HD + lane * 4);
#pragma unroll
        for (int i = 0; i < 4; i++) {
            int t = tq + i;
            if (s < t - WIN || s > t + WIN) continue;  // warp-uniform
            float d = q[i].x * kv.x + q[i].y * kv.y + q[i].z * kv.z + q[i].w * kv.w;
#pragma unroll
            for (int o = 16; o > 0; o >>= 1) d += __shfl_xor_sync(0xffffffffu, d, o);
            d *= scale;
            if (d <= m[i]) {
                float p = __expf(d - m[i]);
                l[i] += p;
                a[i].x += p * vv.x;
                a[i].y += p * vv.y;
                a[i].z += p * vv.z;
                a[i].w += p * vv.w;
            } else {
                float corr = __expf(m[i] - d);
                m[i] = d;
                l[i] = l[i] * corr + 1.f;
                a[i].x = a[i].x * corr + vv.x;
                a[i].y = a[i].y * corr + vv.y;
                a[i].z = a[i].z * corr + vv.z;
                a[i].w = a[i].w * corr + vv.w;
            }
        }
    }
#pragma unroll
    for (int i = 0; i < 4; i++) {
        float inv = 1.f / l[i];
        *(float4*)(O + (size_t)(tq + i) * C_DIM + h * HD + lane * 4) =
            make_float4(rna(a[i].x * inv), rna(a[i].y * inv),
                        rna(a[i].z * inv), rna(a[i].w * inv));
    }
}

// ---------------------------------------------------------------------------
extern "C" void kernel_launch(void* const* d_in, const int* in_sizes, int n_in,
                              void* d_out, int out_size) {
    const float* x  = (const float*)d_in[0];
    const float* wq = (const float*)d_in[1];
    const float* wk = (const float*)d_in[2];
    const float* wv = (const float*)d_in[3];
    const float* wo = (const float*)d_in[4];
    // d_in[5] = sink: constant per softmax row -> cancels; ignored.
    float* out = (float*)d_out;

    float *Q, *Kp, *Vp, *AO, *XR, *W, *WO;
    cudaGetSymbolAddress((void**)&Q,  g_Q);
    cudaGetSymbolAddress((void**)&Kp, g_K);
    cudaGetSymbolAddress((void**)&Vp, g_V);
    cudaGetSymbolAddress((void**)&AO, g_AO);
    cudaGetSymbolAddress((void**)&XR, g_XR);
    cudaGetSymbolAddress((void**)&W,  g_W);
    cudaGetSymbolAddress((void**)&WO, g_WO);

    // one-time prep: rope table + tf32 pre-rounding
    rc_kernel<<<(T_SEQ * HALF + 255) / 256, 256>>>();
    {
        int n4 = T_SEQ * C_DIM / 4;
        round_copy4<<<(n4 + 255) / 256, 256>>>((const float4*)x, (float4*)XR, n4);
        int w4 = C_DIM * C_DIM / 4;
        round_copy4<<<(w4 + 255) / 256, 256>>>((const float4*)wo, (float4*)WO, w4);
        int q4 = C_DIM * QKV_N / 4;
        build_w<<<(q4 + 255) / 256, 256>>>((const float4*)wq, (const float4*)wk,
                                           (const float4*)wv, (float4*)W);
    }

    cudaFuncSetAttribute(gemm_tf32, cudaFuncAttributeMaxDynamicSharedMemorySize,
                         SMEM_BYTES);
    cudaFuncSetAttribute(gemm_tf32, cudaFuncAttributePreferredSharedMemoryCarveout,
                         100);

    // QKV projection (fused, rope in epilogue)
    gemm_tf32<<<dim3(QKV_N / 128, T_SEQ / 128), 256, SMEM_BYTES>>>(XR, W, nullptr,
                                                                   QKV_N, 1);

    attn_kernel<<<dim3(T_SEQ / 32, NH), 256>>>(Q, Kp, Vp, AO);

    // output projection
    gemm_tf32<<<dim3(C_DIM / 128, T_SEQ / 128), 256, SMEM_BYTES>>>(AO, WO, out,
                                                                   C_DIM, 0);
}

// round 9
// speedup vs baseline: 2.2569x; 1.2360x over previous
#include <cuda_runtime.h>
#include <cuda_fp16.h>
#include <math.h>
#include <stdint.h>

#define T_SEQ 4096
#define C_DIM 2048
#define KV_DIM 512
#define QKV_N 3072
#define NH 16
#define NKV 4
#define HD 128
#define HALF 64
#define WIN 64
#define KDIM 2048
#define KT 64                 // 2048 / 32

// Scratch (no runtime allocation allowed)
__device__ float  g_Q[T_SEQ * C_DIM];
__device__ float  g_K[T_SEQ * KV_DIM];
__device__ float  g_V[T_SEQ * KV_DIM];
__device__ __half g_AOH[T_SEQ * C_DIM];        // attention output, fp16
__device__ __half g_XH[T_SEQ * C_DIM];         // x, fp16
__device__ __half g_WH[QKV_N * KDIM];          // [wq|wk|wv]^T  [N][K] fp16
__device__ __half g_WOH[C_DIM * KDIM];         // wo^T          [N][K] fp16
__device__ float2 g_RC[T_SEQ * HALF];          // rope (cos,sin) table

// ---------------------------------------------------------------------------
// One-time prep kernels
// ---------------------------------------------------------------------------
__global__ void rc_kernel() {
    int idx = blockIdx.x * blockDim.x + threadIdx.x;
    if (idx >= T_SEQ * HALF) return;
    int t = idx >> 6;
    int j = idx & 63;
    float inv = powf(10000.0f, -(float)j / (float)HALF);
    float s, c;
    sincosf((float)t * inv, &s, &c);
    g_RC[idx] = make_float2(c, s);
}

__global__ void x_to_half(const float4* __restrict__ src, int n4) {
    int i = blockIdx.x * blockDim.x + threadIdx.x;
    if (i >= n4) return;
    float4 v = src[i];
    __half2* dst = (__half2*)(g_XH + (size_t)i * 4);
    dst[0] = __floats2half2_rn(v.x, v.y);
    dst[1] = __floats2half2_rn(v.z, v.w);
}

// Transpose + convert: g_WH[n][k] = half(src[k][n]); src picked per n-region.
__global__ void build_wt(const float* __restrict__ wq, const float* __restrict__ wk,
                         const float* __restrict__ wv) {
    __shared__ float tile[32][33];
    int k0 = blockIdx.x * 32;
    int n0 = blockIdx.y * 32;
    int tx = threadIdx.x, ty = threadIdx.y;
    const float* src;
    int nb, noff;
    if (n0 < C_DIM)               { src = wq; nb = C_DIM;  noff = 0; }
    else if (n0 < C_DIM + KV_DIM) { src = wk; nb = KV_DIM; noff = C_DIM; }
    else                          { src = wv; nb = KV_DIM; noff = C_DIM + KV_DIM; }
#pragma unroll
    for (int j = 0; j < 4; j++)
        tile[ty + j * 8][tx] =
            src[(size_t)(k0 + ty + j * 8) * nb + (n0 - noff + tx)];
    __syncthreads();
#pragma unroll
    for (int j = 0; j < 4; j++)
        g_WH[(size_t)(n0 + ty + j * 8) * KDIM + k0 + tx] =
            __float2half(tile[tx][ty + j * 8]);
}

__global__ void build_wot(const float* __restrict__ wo) {
    __shared__ float tile[32][33];
    int k0 = blockIdx.x * 32;
    int n0 = blockIdx.y * 32;
    int tx = threadIdx.x, ty = threadIdx.y;
#pragma unroll
    for (int j = 0; j < 4; j++)
        tile[ty + j * 8][tx] = wo[(size_t)(k0 + ty + j * 8) * C_DIM + n0 + tx];
    __syncthreads();
#pragma unroll
    for (int j = 0; j < 4; j++)
        g_WOH[(size_t)(n0 + ty + j * 8) * KDIM + k0 + tx] =
            __float2half(tile[tx][ty + j * 8]);
}

// ---------------------------------------------------------------------------
// FP16 mma.sync GEMM: C[M,N] = A[M,K] @ Bt[N,K]^T, fp32 accumulate.
// CTA tile 128x128x32, 256 threads (8 warps 2x4), warp tile 64x32,
// mma.m16n8k16. Both tiles K-major [row][32 halves], 40-half padded rows
// (20-word stride -> conflict-free frag loads). cp.async 4-stage, 2 CTAs/SM.
// mode 0: plain fp32 store. mode 1: QKV epilogue (rope + route).
// ---------------------------------------------------------------------------
#define STAGES 4
#define SROW 40                               // halves per smem row
#define TILE_BYTES (128 * SROW * 2)           // 10240
#define STAGE_BYTES (2 * TILE_BYTES)          // 20480
#define SMEM_BYTES (STAGES * STAGE_BYTES)     // 81920

__device__ __forceinline__ void cp16(uint32_t dst, const __half* src) {
    asm volatile("cp.async.cg.shared.global [%0], [%1], 16;\n" :: "r"(dst), "l"(src));
}

__device__ __forceinline__ void mma_f16(float c[4], const uint32_t a[4],
                                        const uint32_t b[2]) {
    asm volatile(
        "mma.sync.aligned.m16n8k16.row.col.f32.f16.f16.f32 "
        "{%0,%1,%2,%3}, {%4,%5,%6,%7}, {%8,%9}, {%0,%1,%2,%3};\n"
        : "+f"(c[0]), "+f"(c[1]), "+f"(c[2]), "+f"(c[3])
        : "r"(a[0]), "r"(a[1]), "r"(a[2]), "r"(a[3]), "r"(b[0]), "r"(b[1]));
}

__device__ __forceinline__ void qkv_store(int t, int col, float v0, float v1) {
    if (col < C_DIM) {
        int jj = (col & 127) >> 1;
        float2 cs = g_RC[t * HALF + jj];
        *(float2*)&g_Q[(size_t)t * C_DIM + col] =
            make_float2(v0 * cs.x - v1 * cs.y, v0 * cs.y + v1 * cs.x);
    } else if (col < C_DIM + KV_DIM) {
        int kc = col - C_DIM;
        int jj = (kc & 127) >> 1;
        float2 cs = g_RC[t * HALF + jj];
        *(float2*)&g_K[(size_t)t * KV_DIM + kc] =
            make_float2(v0 * cs.x - v1 * cs.y, v0 * cs.y + v1 * cs.x);
    } else {
        int vc = col - C_DIM - KV_DIM;
        *(float2*)&g_V[(size_t)t * KV_DIM + vc] = make_float2(v0, v1);
    }
}

__global__ void __launch_bounds__(256, 2) gemm_f16(const __half* __restrict__ A,
                                                   const __half* __restrict__ Bt,
                                                   float* __restrict__ C,
                                                   int N, int mode) {
    extern __shared__ char smem[];
    uint32_t smem_u;
    asm("{.reg .u64 t; cvta.to.shared.u64 t, %1; cvt.u32.u64 %0, t;}"
        : "=r"(smem_u) : "l"(smem));

    const int tid = threadIdx.x;
    const int bm = blockIdx.y * 128;
    const int bn = blockIdx.x * 128;
    const int warp = tid >> 5;
    const int lane = tid & 31;
    const int wm = warp >> 2;     // 0..1
    const int wn = warp & 3;      // 0..3
    const int g  = lane >> 2;     // 0..7
    const int tg = lane & 3;      // 0..3

    // loader mapping: 2 tiles x 128 rows x 4 chunks(16B); 4 cp16 per thread
    const int row4 = tid >> 2;    // 0..63 (+64 for second pass)
    const int ch   = tid & 3;
    const __half* ap = A + (size_t)(bm + row4) * KDIM + ch * 8;
    const __half* bp = Bt + (size_t)(bn + row4) * KDIM + ch * 8;
    const uint32_t soff = (uint32_t)((row4 * SROW + ch * 8) * 2);

    float acc[4][4][4];
#pragma unroll
    for (int i = 0; i < 4; i++)
#pragma unroll
        for (int j = 0; j < 4; j++)
#pragma unroll
            for (int r = 0; r < 4; r++) acc[i][j][r] = 0.f;

    // prologue: stages 0..2
#pragma unroll
    for (int s = 0; s < STAGES - 1; s++) {
        uint32_t base = smem_u + (uint32_t)s * STAGE_BYTES;
        cp16(base + soff, ap);
        cp16(base + soff + 64 * SROW * 2, ap + (size_t)64 * KDIM);
        cp16(base + TILE_BYTES + soff, bp);
        cp16(base + TILE_BYTES + soff + 64 * SROW * 2, bp + (size_t)64 * KDIM);
        asm volatile("cp.async.commit_group;\n" ::);
        ap += 32;
        bp += 32;
    }

    int st = 0;
    int wst = STAGES - 1;
    for (int kt = 0; kt < KT; kt++) {
        if (kt + 2 < KT)
            asm volatile("cp.async.wait_group 2;\n" ::);
        else if (kt + 1 < KT)
            asm volatile("cp.async.wait_group 1;\n" ::);
        else
            asm volatile("cp.async.wait_group 0;\n" ::);
        __syncthreads();

        if (kt + STAGES - 1 < KT) {
            uint32_t base = smem_u + (uint32_t)wst * STAGE_BYTES;
            cp16(base + soff, ap);
            cp16(base + soff + 64 * SROW * 2, ap + (size_t)64 * KDIM);
            cp16(base + TILE_BYTES + soff, bp);
            cp16(base + TILE_BYTES + soff + 64 * SROW * 2, bp + (size_t)64 * KDIM);
            asm volatile("cp.async.commit_group;\n" ::);
            ap += 32;
            bp += 32;
            wst = (wst == STAGES - 1) ? 0 : wst + 1;
        }

        const uint32_t* su = (const uint32_t*)(smem + (size_t)st * STAGE_BYTES);
        const uint32_t* bu = (const uint32_t*)(smem + (size_t)st * STAGE_BYTES +
                                               TILE_BYTES);
        st = (st == STAGES - 1) ? 0 : st + 1;

#pragma unroll
        for (int s = 0; s < 2; s++) {       // two k16 steps per k-tile
            const int kw = s * 8 + tg;      // word index within 20-word row
            uint32_t af[4][4], bf[4][2];
#pragma unroll
            for (int i = 0; i < 4; i++) {
                int r0 = (wm * 64 + i * 16 + g) * 20;
                af[i][0] = su[r0 + kw];
                af[i][1] = su[r0 + 8 * 20 + kw];
                af[i][2] = su[r0 + kw + 4];
                af[i][3] = su[r0 + 8 * 20 + kw + 4];
            }
#pragma unroll
            for (int j = 0; j < 4; j++) {
                int c0 = (wn * 32 + j * 8 + g) * 20;
                bf[j][0] = bu[c0 + kw];
                bf[j][1] = bu[c0 + kw + 4];
            }
#pragma unroll
            for (int i = 0; i < 4; i++)
#pragma unroll
                for (int j = 0; j < 4; j++) mma_f16(acc[i][j], af[i], bf[j]);
        }
    }

    if (mode == 0) {
#pragma unroll
        for (int i = 0; i < 4; i++)
#pragma unroll
            for (int j = 0; j < 4; j++) {
                int row = bm + wm * 64 + i * 16 + g;
                int col = bn + wn * 32 + j * 8 + 2 * tg;
                *(float2*)(C + (size_t)row * N + col) =
                    make_float2(acc[i][j][0], acc[i][j][1]);
                *(float2*)(C + (size_t)(row + 8) * N + col) =
                    make_float2(acc[i][j][2], acc[i][j][3]);
            }
    } else {
#pragma unroll
        for (int i = 0; i < 4; i++)
#pragma unroll
            for (int j = 0; j < 4; j++) {
                int row = bm + wm * 64 + i * 16 + g;
                int col = bn + wn * 32 + j * 8 + 2 * tg;
                qkv_store(row, col, acc[i][j][0], acc[i][j][1]);
                qkv_store(row + 8, col, acc[i][j][2], acc[i][j][3]);
            }
    }
}

// ---------------------------------------------------------------------------
// Sliding-window attention: one warp handles 4 adjacent queries of one head,
// sharing each K/V float4 load. Branchy online softmax. sink cancels; ignored.
// Output written as fp16 (feeds final GEMM directly).
// ---------------------------------------------------------------------------
__global__ void __launch_bounds__(256) attn_kernel(const float* __restrict__ Q,
                                                   const float* __restrict__ K,
                                                   const float* __restrict__ V) {
    const int warp = threadIdx.x >> 5;
    const int lane = threadIdx.x & 31;
    const int tq = (blockIdx.x * 8 + warp) * 4;
    const int h = blockIdx.y;
    const int kh = h >> 2;
    const float scale = 0.08838834764831845f;

    float4 q[4];
#pragma unroll
    for (int i = 0; i < 4; i++)
        q[i] = *(const float4*)(Q + (size_t)(tq + i) * C_DIM + h * HD + lane * 4);

    float m[4] = {-1e30f, -1e30f, -1e30f, -1e30f};
    float l[4] = {0.f, 0.f, 0.f, 0.f};
    float4 a[4];
#pragma unroll
    for (int i = 0; i < 4; i++) a[i] = make_float4(0.f, 0.f, 0.f, 0.f);

    int s0 = tq - WIN;      if (s0 < 0) s0 = 0;
    int s1 = tq + 3 + WIN;  if (s1 > T_SEQ - 1) s1 = T_SEQ - 1;

    for (int s = s0; s <= s1; s++) {
        float4 kv = *(const float4*)(K + (size_t)s * KV_DIM + kh * HD + lane * 4);
        float4 vv = *(const float4*)(V + (size_t)s * KV_DIM + kh * HD + lane * 4);
#pragma unroll
        for (int i = 0; i < 4; i++) {
            int t = tq + i;
            if (s < t - WIN || s > t + WIN) continue;  // warp-uniform
            float d = q[i].x * kv.x + q[i].y * kv.y + q[i].z * kv.z + q[i].w * kv.w;
#pragma unroll
            for (int o = 16; o > 0; o >>= 1) d += __shfl_xor_sync(0xffffffffu, d, o);
            d *= scale;
            if (d <= m[i]) {
                float p = __expf(d - m[i]);
                l[i] += p;
                a[i].x += p * vv.x;
                a[i].y += p * vv.y;
                a[i].z += p * vv.z;
                a[i].w += p * vv.w;
            } else {
                float corr = __expf(m[i] - d);
                m[i] = d;
                l[i] = l[i] * corr + 1.f;
                a[i].x = a[i].x * corr + vv.x;
                a[i].y = a[i].y * corr + vv.y;
                a[i].z = a[i].z * corr + vv.z;
                a[i].w = a[i].w * corr + vv.w;
            }
        }
    }
#pragma unroll
    for (int i = 0; i < 4; i++) {
        float inv = 1.f / l[i];
        __half2* ao = (__half2*)(g_AOH + (size_t)(tq + i) * C_DIM + h * HD + lane * 4);
        ao[0] = __floats2half2_rn(a[i].x * inv, a[i].y * inv);
        ao[1] = __floats2half2_rn(a[i].z * inv, a[i].w * inv);
    }
}

// ---------------------------------------------------------------------------
extern "C" void kernel_launch(void* const* d_in, const int* in_sizes, int n_in,
                              void* d_out, int out_size) {
    const float* x  = (const float*)d_in[0];
    const float* wq = (const float*)d_in[1];
    const float* wk = (const float*)d_in[2];
    const float* wv = (const float*)d_in[3];
    const float* wo = (const float*)d_in[4];
    // d_in[5] = sink: constant per softmax row -> cancels; ignored.
    float* out = (float*)d_out;

    float *Q, *Kp, *Vp;
    __half *XH, *WH, *WOH, *AOH;
    cudaGetSymbolAddress((void**)&Q,   g_Q);
    cudaGetSymbolAddress((void**)&Kp,  g_K);
    cudaGetSymbolAddress((void**)&Vp,  g_V);
    cudaGetSymbolAddress((void**)&XH,  g_XH);
    cudaGetSymbolAddress((void**)&WH,  g_WH);
    cudaGetSymbolAddress((void**)&WOH, g_WOH);
    cudaGetSymbolAddress((void**)&AOH, g_AOH);

    // one-time prep: rope table, fp16 conversions, weight transposes
    rc_kernel<<<(T_SEQ * HALF + 255) / 256, 256>>>();
    {
        int n4 = T_SEQ * C_DIM / 4;
        x_to_half<<<(n4 + 255) / 256, 256>>>((const float4*)x, n4);
        build_wt<<<dim3(KDIM / 32, QKV_N / 32), dim3(32, 8)>>>(wq, wk, wv);
        build_wot<<<dim3(KDIM / 32, C_DIM / 32), dim3(32, 8)>>>(wo);
    }

    cudaFuncSetAttribute(gemm_f16, cudaFuncAttributeMaxDynamicSharedMemorySize,
                         SMEM_BYTES);
    cudaFuncSetAttribute(gemm_f16, cudaFuncAttributePreferredSharedMemoryCarveout,
                         100);

    // QKV projection (fused, rope in epilogue)
    gemm_f16<<<dim3(QKV_N / 128, T_SEQ / 128), 256, SMEM_BYTES>>>(XH, WH, nullptr,
                                                                  QKV_N, 1);

    attn_kernel<<<dim3(T_SEQ / 32, NH), 256>>>(Q, Kp, Vp);

    // output projection
    gemm_f16<<<dim3(C_DIM / 128, T_SEQ / 128), 256, SMEM_BYTES>>>(AOH, WOH, out,
                                                                  C_DIM, 0);
}

// round 10
// speedup vs baseline: 2.3561x; 1.0439x over previous
#include <cuda_runtime.h>
#include <cuda_fp16.h>
#include <math.h>
#include <stdint.h>

#define T_SEQ 4096
#define C_DIM 2048
#define KV_DIM 512
#define QKV_N 3072
#define NH 16
#define NKV 4
#define HD 128
#define HALF 64
#define WIN 64
#define KDIM 2048
#define KT 64                 // 2048 / 32

// Scratch (no runtime allocation allowed)
__device__ float  g_Q[T_SEQ * C_DIM];
__device__ float  g_K[T_SEQ * KV_DIM];
__device__ float  g_V[T_SEQ * KV_DIM];
__device__ __half g_AOH[T_SEQ * C_DIM];        // attention output, fp16
__device__ __half g_XH[T_SEQ * C_DIM];         // x, fp16
__device__ __half g_WH[QKV_N * KDIM];          // [wq|wk|wv]^T  [N][K] fp16
__device__ __half g_WOH[C_DIM * KDIM];         // wo^T          [N][K] fp16
__device__ float2 g_RC[T_SEQ * HALF];          // rope (cos,sin) table

// ---------------------------------------------------------------------------
// One-time prep kernels
// ---------------------------------------------------------------------------
__global__ void rc_kernel() {
    int idx = blockIdx.x * blockDim.x + threadIdx.x;
    if (idx >= T_SEQ * HALF) return;
    int t = idx >> 6;
    int j = idx & 63;
    float inv = powf(10000.0f, -(float)j / (float)HALF);
    float s, c;
    sincosf((float)t * inv, &s, &c);
    g_RC[idx] = make_float2(c, s);
}

__global__ void x_to_half(const float4* __restrict__ src, int n4) {
    int i = blockIdx.x * blockDim.x + threadIdx.x;
    if (i >= n4) return;
    float4 v = src[i];
    __half2* dst = (__half2*)(g_XH + (size_t)i * 4);
    dst[0] = __floats2half2_rn(v.x, v.y);
    dst[1] = __floats2half2_rn(v.z, v.w);
}

// Transpose + convert: g_WH[n][k] = half(src[k][n]); src picked per n-region.
__global__ void build_wt(const float* __restrict__ wq, const float* __restrict__ wk,
                         const float* __restrict__ wv) {
    __shared__ float tile[32][33];
    int k0 = blockIdx.x * 32;
    int n0 = blockIdx.y * 32;
    int tx = threadIdx.x, ty = threadIdx.y;
    const float* src;
    int nb, noff;
    if (n0 < C_DIM)               { src = wq; nb = C_DIM;  noff = 0; }
    else if (n0 < C_DIM + KV_DIM) { src = wk; nb = KV_DIM; noff = C_DIM; }
    else                          { src = wv; nb = KV_DIM; noff = C_DIM + KV_DIM; }
#pragma unroll
    for (int j = 0; j < 4; j++)
        tile[ty + j * 8][tx] =
            src[(size_t)(k0 + ty + j * 8) * nb + (n0 - noff + tx)];
    __syncthreads();
#pragma unroll
    for (int j = 0; j < 4; j++)
        g_WH[(size_t)(n0 + ty + j * 8) * KDIM + k0 + tx] =
            __float2half(tile[tx][ty + j * 8]);
}

__global__ void build_wot(const float* __restrict__ wo) {
    __shared__ float tile[32][33];
    int k0 = blockIdx.x * 32;
    int n0 = blockIdx.y * 32;
    int tx = threadIdx.x, ty = threadIdx.y;
#pragma unroll
    for (int j = 0; j < 4; j++)
        tile[ty + j * 8][tx] = wo[(size_t)(k0 + ty + j * 8) * C_DIM + n0 + tx];
    __syncthreads();
#pragma unroll
    for (int j = 0; j < 4; j++)
        g_WOH[(size_t)(n0 + ty + j * 8) * KDIM + k0 + tx] =
            __float2half(tile[tx][ty + j * 8]);
}

// ---------------------------------------------------------------------------
// FP16 mma.sync GEMM with ldmatrix fragment loads.
// C[M,N] = A[M,K] @ Bt[N,K]^T, fp32 accumulate.
// CTA tile 128x128x32, 256 threads (8 warps 2x4), warp tile 64x32,
// mma.m16n8k16. Both tiles K-major, 40-half padded rows (conflict-free
// LDSM: row word-offsets {0,4,..,28} mod 32). cp.async 5-stage, 2 CTAs/SM.
// mode 0: plain fp32 store. mode 1: QKV epilogue (rope + route).
// ---------------------------------------------------------------------------
#define STAGES 5
#define SROW 40                               // halves per smem row
#define TILE_BYTES (128 * SROW * 2)           // 10240
#define STAGE_BYTES (2 * TILE_BYTES)          // 20480
#define SMEM_BYTES (STAGES * STAGE_BYTES)     // 102400

__device__ __forceinline__ void cp16(uint32_t dst, const __half* src) {
    asm volatile("cp.async.cg.shared.global [%0], [%1], 16;\n" :: "r"(dst), "l"(src));
}

#define LDSM4(r0, r1, r2, r3, addr)                                            \
    asm volatile("ldmatrix.sync.aligned.m8n8.x4.shared.b16 {%0,%1,%2,%3}, [%4];" \
                 : "=r"(r0), "=r"(r1), "=r"(r2), "=r"(r3) : "r"(addr))

__device__ __forceinline__ void mma_f16(float c[4], const uint32_t a[4],
                                        const uint32_t b[2]) {
    asm volatile(
        "mma.sync.aligned.m16n8k16.row.col.f32.f16.f16.f32 "
        "{%0,%1,%2,%3}, {%4,%5,%6,%7}, {%8,%9}, {%0,%1,%2,%3};\n"
        : "+f"(c[0]), "+f"(c[1]), "+f"(c[2]), "+f"(c[3])
        : "r"(a[0]), "r"(a[1]), "r"(a[2]), "r"(a[3]), "r"(b[0]), "r"(b[1]));
}

__device__ __forceinline__ void qkv_store(int t, int col, float v0, float v1) {
    if (col < C_DIM) {
        int jj = (col & 127) >> 1;
        float2 cs = g_RC[t * HALF + jj];
        *(float2*)&g_Q[(size_t)t * C_DIM + col] =
            make_float2(v0 * cs.x - v1 * cs.y, v0 * cs.y + v1 * cs.x);
    } else if (col < C_DIM + KV_DIM) {
        int kc = col - C_DIM;
        int jj = (kc & 127) >> 1;
        float2 cs = g_RC[t * HALF + jj];
        *(float2*)&g_K[(size_t)t * KV_DIM + kc] =
            make_float2(v0 * cs.x - v1 * cs.y, v0 * cs.y + v1 * cs.x);
    } else {
        int vc = col - C_DIM - KV_DIM;
        *(float2*)&g_V[(size_t)t * KV_DIM + vc] = make_float2(v0, v1);
    }
}

__global__ void __launch_bounds__(256, 2) gemm_f16(const __half* __restrict__ A,
                                                   const __half* __restrict__ Bt,
                                                   float* __restrict__ C,
                                                   int N, int mode) {
    extern __shared__ char smem[];
    uint32_t smem_u;
    asm("{.reg .u64 t; cvta.to.shared.u64 t, %1; cvt.u32.u64 %0, t;}"
        : "=r"(smem_u) : "l"(smem));

    const int tid = threadIdx.x;
    const int bm = blockIdx.y * 128;
    const int bn = blockIdx.x * 128;
    const int warp = tid >> 5;
    const int lane = tid & 31;
    const int wm = warp >> 2;     // 0..1
    const int wn = warp & 3;      // 0..3
    const int g  = lane >> 2;     // 0..7
    const int tg = lane & 3;      // 0..3

    // ldmatrix per-lane address constants (byte offsets within stage)
    const int mi = lane >> 3;     // matrix index 0..3
    const int rw = lane & 7;      // row within matrix
    // A: m0=rows0-7/k0-7, m1=rows8-15/k0-7, m2=rows0-7/k8-15, m3=rows8-15/k8-15
    const uint32_t aoff0 =
        (uint32_t)(((wm * 64 + ((mi & 1) << 3) + rw) * SROW + ((mi >> 1) << 3)) * 2);
    // B: m0=(j,k0-7), m1=(j,k8-15), m2=(j+1,k0-7), m3=(j+1,k8-15)
    const uint32_t boff0 =
        (uint32_t)(((wn * 32 + ((mi >> 1) << 3) + rw) * SROW + ((mi & 1) << 3)) * 2) +
        TILE_BYTES;

    // loader mapping: 2 tiles x 128 rows x 4 chunks(16B); 4 cp16 per thread
    const int row4 = tid >> 2;    // 0..63 (+64 for second pass)
    const int ch   = tid & 3;
    const __half* ap = A + (size_t)(bm + row4) * KDIM + ch * 8;
    const __half* bp = Bt + (size_t)(bn + row4) * KDIM + ch * 8;
    const uint32_t soff = (uint32_t)((row4 * SROW + ch * 8) * 2);

    float acc[4][4][4];
#pragma unroll
    for (int i = 0; i < 4; i++)
#pragma unroll
        for (int j = 0; j < 4; j++)
#pragma unroll
            for (int r = 0; r < 4; r++) acc[i][j][r] = 0.f;

    // prologue: stages 0..STAGES-2
#pragma unroll
    for (int s = 0; s < STAGES - 1; s++) {
        uint32_t base = smem_u + (uint32_t)s * STAGE_BYTES;
        cp16(base + soff, ap);
        cp16(base + soff + 64 * SROW * 2, ap + (size_t)64 * KDIM);
        cp16(base + TILE_BYTES + soff, bp);
        cp16(base + TILE_BYTES + soff + 64 * SROW * 2, bp + (size_t)64 * KDIM);
        asm volatile("cp.async.commit_group;\n" ::);
        ap += 32;
        bp += 32;
    }

    int st = 0;
    int wst = STAGES - 1;
    for (int kt = 0; kt < KT; kt++) {
        // wait: stage kt's group must be complete (N = min(STAGES-2, KT-1-kt))
        if (kt < KT - 3)
            asm volatile("cp.async.wait_group 3;\n" ::);
        else if (kt == KT - 3)
            asm volatile("cp.async.wait_group 2;\n" ::);
        else if (kt == KT - 2)
            asm volatile("cp.async.wait_group 1;\n" ::);
        else
            asm volatile("cp.async.wait_group 0;\n" ::);
        __syncthreads();

        if (kt + STAGES - 1 < KT) {
            uint32_t base = smem_u + (uint32_t)wst * STAGE_BYTES;
            cp16(base + soff, ap);
            cp16(base + soff + 64 * SROW * 2, ap + (size_t)64 * KDIM);
            cp16(base + TILE_BYTES + soff, bp);
            cp16(base + TILE_BYTES + soff + 64 * SROW * 2, bp + (size_t)64 * KDIM);
            asm volatile("cp.async.commit_group;\n" ::);
            ap += 32;
            bp += 32;
            wst = (wst == STAGES - 1) ? 0 : wst + 1;
        }

        const uint32_t sbase = smem_u + (uint32_t)st * STAGE_BYTES;
        st = (st == STAGES - 1) ? 0 : st + 1;

#pragma unroll
        for (int s = 0; s < 2; s++) {       // two k16 steps per k-tile
            uint32_t af[4][4], bf[4][2];
#pragma unroll
            for (int i = 0; i < 4; i++)
                LDSM4(af[i][0], af[i][1], af[i][2], af[i][3],
                      sbase + aoff0 + (uint32_t)(i * 16 * SROW * 2 + s * 32));
#pragma unroll
            for (int jp = 0; jp < 2; jp++)
                LDSM4(bf[jp * 2][0], bf[jp * 2][1], bf[jp * 2 + 1][0],
                      bf[jp * 2 + 1][1],
                      sbase + boff0 + (uint32_t)(jp * 16 * SROW * 2 + s * 32));
#pragma unroll
            for (int i = 0; i < 4; i++)
#pragma unroll
                for (int j = 0; j < 4; j++) mma_f16(acc[i][j], af[i], bf[j]);
        }
    }

    if (mode == 0) {
#pragma unroll
        for (int i = 0; i < 4; i++)
#pragma unroll
            for (int j = 0; j < 4; j++) {
                int row = bm + wm * 64 + i * 16 + g;
                int col = bn + wn * 32 + j * 8 + 2 * tg;
                *(float2*)(C + (size_t)row * N + col) =
                    make_float2(acc[i][j][0], acc[i][j][1]);
                *(float2*)(C + (size_t)(row + 8) * N + col) =
                    make_float2(acc[i][j][2], acc[i][j][3]);
            }
    } else {
#pragma unroll
        for (int i = 0; i < 4; i++)
#pragma unroll
            for (int j = 0; j < 4; j++) {
                int row = bm + wm * 64 + i * 16 + g;
                int col = bn + wn * 32 + j * 8 + 2 * tg;
                qkv_store(row, col, acc[i][j][0], acc[i][j][1]);
                qkv_store(row + 8, col, acc[i][j][2], acc[i][j][3]);
            }
    }
}

// ---------------------------------------------------------------------------
// Sliding-window attention: one warp handles 4 adjacent queries of one head,
// sharing each K/V float4 load. Branchy online softmax. sink cancels; ignored.
// Output written as fp16 (feeds final GEMM directly).
// ---------------------------------------------------------------------------
__global__ void __launch_bounds__(256) attn_kernel(const float* __restrict__ Q,
                                                   const float* __restrict__ K,
                                                   const float* __restrict__ V) {
    const int warp = threadIdx.x >> 5;
    const int lane = threadIdx.x & 31;
    const int tq = (blockIdx.x * 8 + warp) * 4;
    const int h = blockIdx.y;
    const int kh = h >> 2;
    const float scale = 0.08838834764831845f;

    float4 q[4];
#pragma unroll
    for (int i = 0; i < 4; i++)
        q[i] = *(const float4*)(Q + (size_t)(tq + i) * C_DIM + h * HD + lane * 4);

    float m[4] = {-1e30f, -1e30f, -1e30f, -1e30f};
    float l[4] = {0.f, 0.f, 0.f, 0.f};
    float4 a[4];
#pragma unroll
    for (int i = 0; i < 4; i++) a[i] = make_float4(0.f, 0.f, 0.f, 0.f);

    int s0 = tq - WIN;      if (s0 < 0) s0 = 0;
    int s1 = tq + 3 + WIN;  if (s1 > T_SEQ - 1) s1 = T_SEQ - 1;

    for (int s = s0; s <= s1; s++) {
        float4 kv = *(const float4*)(K + (size_t)s * KV_DIM + kh * HD + lane * 4);
        float4 vv = *(const float4*)(V + (size_t)s * KV_DIM + kh * HD + lane * 4);
#pragma unroll
        for (int i = 0; i < 4; i++) {
            int t = tq + i;
            if (s < t - WIN || s > t + WIN) continue;  // warp-uniform
            float d = q[i].x * kv.x + q[i].y * kv.y + q[i].z * kv.z + q[i].w * kv.w;
#pragma unroll
            for (int o = 16; o > 0; o >>= 1) d += __shfl_xor_sync(0xffffffffu, d, o);
            d *= scale;
            if (d <= m[i]) {
                float p = __expf(d - m[i]);
                l[i] += p;
                a[i].x += p * vv.x;
                a[i].y += p * vv.y;
                a[i].z += p * vv.z;
                a[i].w += p * vv.w;
            } else {
                float corr = __expf(m[i] - d);
                m[i] = d;
                l[i] = l[i] * corr + 1.f;
                a[i].x = a[i].x * corr + vv.x;
                a[i].y = a[i].y * corr + vv.y;
                a[i].z = a[i].z * corr + vv.z;
                a[i].w = a[i].w * corr + vv.w;
            }
        }
    }
#pragma unroll
    for (int i = 0; i < 4; i++) {
        float inv = 1.f / l[i];
        __half2* ao = (__half2*)(g_AOH + (size_t)(tq + i) * C_DIM + h * HD + lane * 4);
        ao[0] = __floats2half2_rn(a[i].x * inv, a[i].y * inv);
        ao[1] = __floats2half2_rn(a[i].z * inv, a[i].w * inv);
    }
}

// ---------------------------------------------------------------------------
extern "C" void kernel_launch(void* const* d_in, const int* in_sizes, int n_in,
                              void* d_out, int out_size) {
    const float* x  = (const float*)d_in[0];
    const float* wq = (const float*)d_in[1];
    const float* wk = (const float*)d_in[2];
    const float* wv = (const float*)d_in[3];
    const float* wo = (const float*)d_in[4];
    // d_in[5] = sink: constant per softmax row -> cancels; ignored.
    float* out = (float*)d_out;

    float *Q, *Kp, *Vp;
    __half *XH, *WH, *WOH, *AOH;
    cudaGetSymbolAddress((void**)&Q,   g_Q);
    cudaGetSymbolAddress((void**)&Kp,  g_K);
    cudaGetSymbolAddress((void**)&Vp,  g_V);
    cudaGetSymbolAddress((void**)&XH,  g_XH);
    cudaGetSymbolAddress((void**)&WH,  g_WH);
    cudaGetSymbolAddress((void**)&WOH, g_WOH);
    cudaGetSymbolAddress((void**)&AOH, g_AOH);

    // one-time prep: rope table, fp16 conversions, weight transposes
    rc_kernel<<<(T_SEQ * HALF + 255) / 256, 256>>>();
    {
        int n4 = T_SEQ * C_DIM / 4;
        x_to_half<<<(n4 + 255) / 256, 256>>>((const float4*)x, n4);
        build_wt<<<dim3(KDIM / 32, QKV_N / 32), dim3(32, 8)>>>(wq, wk, wv);
        build_wot<<<dim3(KDIM / 32, C_DIM / 32), dim3(32, 8)>>>(wo);
    }

    cudaFuncSetAttribute(gemm_f16, cudaFuncAttributeMaxDynamicSharedMemorySize,
                         SMEM_BYTES);
    cudaFuncSetAttribute(gemm_f16, cudaFuncAttributePreferredSharedMemoryCarveout,
                         100);

    // QKV projection (fused, rope in epilogue)
    gemm_f16<<<dim3(QKV_N / 128, T_SEQ / 128), 256, SMEM_BYTES>>>(XH, WH, nullptr,
                                                                  QKV_N, 1);

    attn_kernel<<<dim3(T_SEQ / 32, NH), 256>>>(Q, Kp, Vp);

    // output projection
    gemm_f16<<<dim3(C_DIM / 128, T_SEQ / 128), 256, SMEM_BYTES>>>(AOH, WOH, out,
                                                                  C_DIM, 0);
}